// round 2
// baseline (speedup 1.0000x reference)
#include <cuda_runtime.h>

#define K 19
#define L 2048
#define B 512
#define START_ID 17
#define PAD_ID 18
#define NEG -1000.0f
#define BPSTRIDE 20

// 1 if mask elements are 4 bytes (int32/float32), 0 if 1 byte (bool/uint8)
__device__ int g_elt4;

// Detect mask element size: for 4-byte 0/1 values (int 1 = 01 00 00 00,
// float 1.0 = 00 00 80 3F), every byte at offset ≡ 1 (mod 4) is zero.
// For a 1-byte bool mask with contiguous-prefix rows (len >= 1), the first
// 64KB (16+ rows) almost surely has a nonzero byte at such an offset.
__global__ void detect_kernel(const unsigned char* __restrict__ m) {
    __shared__ int found;
    if (threadIdx.x == 0) found = 0;
    __syncthreads();
    int f = 0;
    for (int i = threadIdx.x * 4 + 1; i < 65536; i += blockDim.x * 4)
        f |= m[i];
    if (f) found = 1;
    __syncthreads();
    if (threadIdx.x == 0) g_elt4 = found ? 0 : 1;
}

__global__ void __launch_bounds__(32, 4) viterbi_kernel(
    const float* __restrict__ P,          // [B, L, K]
    const float* __restrict__ Tm,         // [K, K], T[j*K+k] = prev k -> cur j
    const unsigned char* __restrict__ mask,
    float* __restrict__ out)              // [B, L] float32 (cast int path)
{
    __shared__ unsigned char bp[L * BPSTRIDE];  // backpointers, 40960 B

    const int b = blockIdx.x;
    const int lane = threadIdx.x;
    const int j = (lane < K) ? lane : 0;

    // T row for this lane's output state, held in registers
    float Trow[K];
#pragma unroll
    for (int k = 0; k < K; ++k) Trow[k] = Tm[j * K + k];

    // ---- sequence length: count nonzero mask elements in this row ----
    int len = 0;
    if (g_elt4) {
        const unsigned int* m = (const unsigned int*)mask + (size_t)b * L;
        for (int i = lane; i < L; i += 32) len += (m[i] != 0u);
    } else {
        const unsigned char* m = mask + (size_t)b * L;
        for (int i = lane; i < L; i += 32) len += (m[i] != 0);
    }
#pragma unroll
    for (int o = 16; o; o >>= 1) len += __shfl_xor_sync(0xffffffffu, len, o);

    // ---- DP init (replicated in every lane) ----
    float DP[K];
#pragma unroll
    for (int k = 0; k < K; ++k) DP[k] = (k == START_ID) ? 0.0f : NEG;

    const float* Pb = P + (size_t)b * L * K;

    // emission prefetch pipeline, depth 4 (~300+ cycles of lead)
    float ebuf[4];
#pragma unroll
    for (int i = 0; i < 4; ++i) {
        int tt = (i < len) ? i : (len - 1);
        ebuf[i] = Pb[tt * K + j];
    }

    // ---- forward pass ----
    for (int t = 0; t < len; ++t) {
        float emit = ebuf[t & 3];
        {
            int tp = t + 4;
            if (tp >= len) tp = len - 1;
            ebuf[t & 3] = Pb[tp * K + j];
        }

        float s[K], v[K];
#pragma unroll
        for (int k = 0; k < K; ++k) { s[k] = DP[k] + Trow[k]; v[k] = s[k]; }

        // balanced max tree (depth 5)
#pragma unroll
        for (int w = 1; w < K; w *= 2)
#pragma unroll
            for (int i = 0; i + w < K; i += 2 * w)
                v[i] = fmaxf(v[i], v[i + w]);
        float best = v[0];

        // first-occurrence argmax (off the critical path)
        unsigned mb = 0u;
#pragma unroll
        for (int k = 0; k < K; ++k) mb |= (s[k] == best) ? (1u << k) : 0u;
        int arg = __ffs(mb) - 1;
        if (lane < K) bp[t * BPSTRIDE + lane] = (unsigned char)arg;

        float nd = best + emit;

        // re-replicate DP to all lanes
#pragma unroll
        for (int k = 0; k < K; ++k) DP[k] = __shfl_sync(0xffffffffu, nd, k);
    }

    __syncwarp();

    // ---- final transition into PAD, argmax for last tag ----
    float bestf = DP[0] + Tm[PAD_ID * K + 0];
    int last = 0;
#pragma unroll
    for (int k = 1; k < K; ++k) {
        float v2 = DP[k] + Tm[PAD_ID * K + k];
        if (v2 > bestf) { bestf = v2; last = k; }
    }

    float* ob = out + (size_t)b * L;

    // pad tail with -1.0f (parallel across lanes)
    for (int t = len + lane; t < L; t += 32) ob[t] = -1.0f;

    // ---- backtrack (lane 0, dependent SMEM chain) ----
    if (lane == 0) {
        int c = last;
        for (int t = len - 1; t > 0; --t) {
            ob[t] = (float)c;
            c = bp[t * BPSTRIDE + c];
        }
        ob[0] = (float)c;
    }
}

extern "C" void kernel_launch(void* const* d_in, const int* in_sizes, int n_in,
                              void* d_out, int out_size) {
    const float* P = (const float*)d_in[0];
    const float* T = (const float*)d_in[1];
    const unsigned char* mask = (const unsigned char*)d_in[2];
    float* out = (float*)d_out;

    detect_kernel<<<1, 256>>>(mask);
    viterbi_kernel<<<B, 32>>>(P, T, mask, out);
}

// round 3
// speedup vs baseline: 1.5176x; 1.5176x over previous
#include <cuda_runtime.h>

#define K 19
#define L 2048
#define B 512
#define START_ID 17
#define PAD_ID 18
#define NEG -1000.0f
#define BPST 20
#define NTHREADS 128
#define NW 4          // warps per block
#define SEG 512       // L / NW backtrack segment size

// 1 if mask elements are 4 bytes (int32/float32), 0 if 1 byte (bool/uint8)
__device__ int g_elt4;

__global__ void detect_kernel(const unsigned char* __restrict__ m) {
    __shared__ int found;
    if (threadIdx.x == 0) found = 0;
    __syncthreads();
    int f = 0;
    for (int i = threadIdx.x * 4 + 1; i < 65536; i += blockDim.x * 4)
        f |= m[i];
    if (f) found = 1;
    __syncthreads();
    if (threadIdx.x == 0) g_elt4 = found ? 0 : 1;
}

__global__ void __launch_bounds__(NTHREADS, 4) viterbi_kernel(
    const float* __restrict__ P,          // [B, L, K]
    const float* __restrict__ Tm,         // [K, K]: T[j*K+k], prev k -> cur j
    const unsigned char* __restrict__ mask,
    float* __restrict__ out)              // [B, L] float32
{
    __shared__ unsigned char bp[L * BPST];      // backpointers, 40960 B
    __shared__ float dpbuf[2][20];              // double-buffered DP vector
    __shared__ int s_len, s_last;
    __shared__ unsigned char fmap[NW][K];       // segment-entry map
    __shared__ unsigned char eseg[NW];          // resolved segment end states

    const int b = blockIdx.x;
    const int tid = threadIdx.x;
    const int wid = tid >> 5;
    const int lane = tid & 31;

    // ---- sequence length (warp 0) ----
    if (wid == 0) {
        int len = 0;
        if (g_elt4) {
            const unsigned int* m = (const unsigned int*)mask + (size_t)b * L;
            for (int i = lane; i < L; i += 32) len += (m[i] != 0u);
        } else {
            const unsigned char* m = mask + (size_t)b * L;
            for (int i = lane; i < L; i += 32) len += (m[i] != 0);
        }
#pragma unroll
        for (int o = 16; o; o >>= 1) len += __shfl_xor_sync(0xffffffffu, len, o);
        if (lane == 0) s_len = len;
    }
    __syncthreads();
    const int len = s_len;

    // ================= FORWARD (warp 0 only) =================
    if (wid == 0) {
        const int j = (lane < K) ? lane : 0;

        float Trow[K];
#pragma unroll
        for (int k = 0; k < K; ++k) Trow[k] = Tm[j * K + k];

        if (lane < 20) dpbuf[0][lane] = (lane == START_ID) ? 0.0f : NEG;
        __syncwarp();

        const float* Pb = P + (size_t)b * L * K;

        // emission prefetch pipeline, depth 4
        float ebuf[4];
#pragma unroll
        for (int i = 0; i < 4; ++i) {
            int tt = (i < len) ? i : (len - 1);
            ebuf[i] = __ldg(Pb + tt * K + j);
        }

        int cur = 0;
        for (int t = 0; t < len; ++t) {
            float emit = ebuf[t & 3];
            {
                int tp = t + 4;
                if (tp >= len) tp = len - 1;
                ebuf[t & 3] = __ldg(Pb + tp * K + j);
            }

            // load full DP vector (20 floats = 5x LDS.128, broadcast)
            float d[20];
            *(float4*)&d[0]  = *(const float4*)&dpbuf[cur][0];
            *(float4*)&d[4]  = *(const float4*)&dpbuf[cur][4];
            *(float4*)&d[8]  = *(const float4*)&dpbuf[cur][8];
            *(float4*)&d[12] = *(const float4*)&dpbuf[cur][12];
            *(float4*)&d[16] = *(const float4*)&dpbuf[cur][16];

            float s[K], v[K];
#pragma unroll
            for (int k = 0; k < K; ++k) { s[k] = d[k] + Trow[k]; v[k] = s[k]; }

            // balanced max tree (depth 5, exact: max is associative)
#pragma unroll
            for (int w = 1; w < K; w *= 2)
#pragma unroll
                for (int i = 0; i + w < K; i += 2 * w)
                    v[i] = fmaxf(v[i], v[i + w]);
            const float best = v[0];

            // first-occurrence argmax (off critical path)
            unsigned mb = 0u;
#pragma unroll
            for (int k = 0; k < K; ++k) mb |= (s[k] == best) ? (1u << k) : 0u;
            const int arg = __ffs(mb) - 1;
            if (lane < K) bp[t * BPST + lane] = (unsigned char)arg;

            const float nd = best + emit;

            const int nxt = cur ^ 1;
            if (lane < 20) dpbuf[nxt][lane] = (lane < K) ? nd : NEG;
            __syncwarp();
            cur = nxt;
        }

        // final transition into PAD + argmax (lane 0)
        if (lane == 0) {
            float bestf = dpbuf[cur][0] + Tm[PAD_ID * K + 0];
            int last = 0;
#pragma unroll
            for (int k = 1; k < K; ++k) {
                float v2 = dpbuf[cur][k] + Tm[PAD_ID * K + k];
                if (v2 > bestf) { bestf = v2; last = k; }
            }
            s_last = last;
        }
    }
    __syncthreads();

    // ================= BACKTRACK (all warps) =================
    float* ob = out + (size_t)b * L;

    // pad tail with -1.0f (parallel across all threads)
    for (int t = len + tid; t < L; t += NTHREADS) ob[t] = -1.0f;

    const int nseg = (len + SEG - 1) / SEG;

    // pass 1: for each (segment, end-state) chase chain to segment start
    if (tid < nseg * K) {
        const int seg = tid / K;
        const int e   = tid - seg * K;
        const int t0  = seg * SEG;
        const int t1  = min(t0 + SEG, len);
        int c = e;
        for (int t = t1 - 2; t >= t0; --t) c = bp[(t + 1) * BPST + c];
        fmap[seg][e] = (unsigned char)c;   // = path[t0] given path[t1-1]=e
    }
    __syncthreads();

    // resolve segment end states top-down (cheap: <= NW dependent lookups)
    if (tid == 0) {
        int e = s_last;
        eseg[nseg - 1] = (unsigned char)e;
        for (int i = nseg - 1; i > 0; --i) {
            const int t0 = i * SEG;
            const int pc = fmap[i][e];          // path[t0]
            e = bp[t0 * BPST + pc];             // path[t0-1]
            eseg[i - 1] = (unsigned char)e;
        }
    }
    __syncthreads();

    // pass 2: each warp decodes its segment (lane 0 walks, writes output)
    if (wid < nseg && lane == 0) {
        const int t0 = wid * SEG;
        const int t1 = min(t0 + SEG, len);
        int c = eseg[wid];
        ob[t1 - 1] = (float)c;
        for (int t = t1 - 2; t >= t0; --t) {
            c = bp[(t + 1) * BPST + c];
            ob[t] = (float)c;
        }
    }
}

extern "C" void kernel_launch(void* const* d_in, const int* in_sizes, int n_in,
                              void* d_out, int out_size) {
    const float* P = (const float*)d_in[0];
    const float* T = (const float*)d_in[1];
    const unsigned char* mask = (const unsigned char*)d_in[2];
    float* out = (float*)d_out;

    detect_kernel<<<1, 256>>>(mask);
    viterbi_kernel<<<B, NTHREADS>>>(P, T, mask, out);
}